// round 2
// baseline (speedup 1.0000x reference)
#include <cuda_runtime.h>
#include <cuda_bf16.h>

#define CKD 128
typedef unsigned long long ull;

// ---------------- static scratch ----------------
__device__ float  g_xs[(long)16*8191*128];
__device__ float  g_d [(long)16*4096*128];
__device__ float  g_ud[(long)16*8191*128];
__device__ float  g_us[(long)16*8191*128];
__device__ float2 g_part[(long)8*16*64*128];
__device__ float2 g_ftd[16*64*128];
__device__ float2 g_ftx[16*64*128];
__device__ float2 g_oud[16*64*128];
__device__ float2 g_ous[16*64*128];
__device__ float2 g_wt[(long)3*64*128*128];
__device__ float2 g_tw[4096+64];

// ---------------- f32x2 helpers ----------------
__device__ __forceinline__ ull pk2(float x, float y){
    ull r; asm("mov.b64 %0, {%1, %2};" : "=l"(r) : "f"(x), "f"(y)); return r;
}
__device__ __forceinline__ float2 up2(ull v){
    float2 r; asm("mov.b64 {%0, %1}, %2;" : "=f"(r.x), "=f"(r.y) : "l"(v)); return r;
}
__device__ __forceinline__ void ffma2(ull &acc, ull a, ull b){
    asm("fma.rn.f32x2 %0, %1, %2, %0;" : "+l"(acc) : "l"(a), "l"(b));
}

// ---------------- base twiddle table: g_tw[r] = (cos(2*pi*r/4096), -sin(...)) ----------------
__global__ void k_base(){
    int r = blockIdx.x*blockDim.x + threadIdx.x;
    if (r >= 4096) return;
    float s, c;
    sincospif(r/2048.0f, &s, &c);
    g_tw[r] = make_float2(c, -s);
    if (r < 64) g_tw[4096+r] = make_float2(0.f, 0.f);  // pad
}

// ---------------- weight transpose (i,o,m) -> (m,i,o) complex ----------------
__global__ void k_wtrans(const float* __restrict__ wr, const float* __restrict__ wi, int mat){
    long idx = blockIdx.x*(long)blockDim.x + threadIdx.x;
    if (idx >= (long)64*128*128) return;
    int m = (int)(idx & 63);
    int o = (int)((idx >> 6) & 127);
    int i = (int)(idx >> 13);
    g_wt[((long)mat*64 + m)*16384 + (long)i*128 + o] = make_float2(wr[idx], wi[idx]);
}

// ---------------- wavelet decompose ----------------
__global__ void __launch_bounds__(256) k_decompose(const float* __restrict__ xext, long xoff,
        long soff, const float* __restrict__ ecs, const float* __restrict__ ecd, int nh){
    __shared__ ull f[128];
    if (threadIdx.x < 128) f[threadIdx.x] = pk2(ecs[threadIdx.x], ecd[threadIdx.x]);
    __syncthreads();
    long idx = blockIdx.x*(long)blockDim.x + threadIdx.x;
    if (idx >= (long)16*nh*16) return;
    int c = (int)(idx & 15);
    long bt = idx >> 4;
    const float* xin = xext ? xext : (g_xs + xoff);
    const float* pe = xin + bt*2*CKD + c*8;
    float4 e0 = *(const float4*)(pe);
    float4 e1 = *(const float4*)(pe+4);
    float4 o0 = *(const float4*)(pe+CKD);
    float4 o1 = *(const float4*)(pe+CKD+4);
    float xa[16] = {e0.x,e0.y,e0.z,e0.w, e1.x,e1.y,e1.z,e1.w,
                    o0.x,o0.y,o0.z,o0.w, o1.x,o1.y,o1.z,o1.w};
    ull acc[8];
    #pragma unroll
    for (int ko=0;ko<8;++ko) acc[ko]=0ull;
    #pragma unroll
    for (int j=0;j<16;++j){
        ull vj = pk2(xa[j], xa[j]);
        #pragma unroll
        for (int ko=0;ko<8;++ko) ffma2(acc[ko], vj, f[j*8+ko]);
    }
    float* ps = g_xs + soff + bt*CKD + c*8;
    float* pd = g_d         + bt*CKD + c*8;
    float2 r0=up2(acc[0]), r1=up2(acc[1]), r2=up2(acc[2]), r3=up2(acc[3]);
    float2 r4=up2(acc[4]), r5=up2(acc[5]), r6=up2(acc[6]), r7=up2(acc[7]);
    *(float4*)ps     = make_float4(r0.x,r1.x,r2.x,r3.x);
    *(float4*)(ps+4) = make_float4(r4.x,r5.x,r6.x,r7.x);
    *(float4*)pd     = make_float4(r0.y,r1.y,r2.y,r3.y);
    *(float4*)(pd+4) = make_float4(r4.y,r5.y,r6.y,r7.y);
}

// ---------------- reconstruction ----------------
__global__ void __launch_bounds__(256) k_recon(long xoff, long uoff,
        float* __restrict__ oext, long ooff,
        const float* __restrict__ rce, const float* __restrict__ rco, int nh){
    __shared__ ull f[128];
    if (threadIdx.x < 128) f[threadIdx.x] = pk2(rce[threadIdx.x], rco[threadIdx.x]);
    __syncthreads();
    long idx = blockIdx.x*(long)blockDim.x + threadIdx.x;
    if (idx >= (long)16*nh*16) return;
    int c = (int)(idx & 15);
    long bt = idx >> 4;
    const float* px = g_xs + xoff + bt*CKD + c*8;
    const float* pu = g_us + uoff + bt*CKD + c*8;
    const float* pw = g_ud + uoff + bt*CKD + c*8;
    float4 a0 = *(const float4*)px,     u0 = *(const float4*)pu;
    float4 a1 = *(const float4*)(px+4), u1 = *(const float4*)(pu+4);
    float4 w0 = *(const float4*)pw,     w1 = *(const float4*)(pw+4);
    float xc[16] = {a0.x+u0.x, a0.y+u0.y, a0.z+u0.z, a0.w+u0.w,
                    a1.x+u1.x, a1.y+u1.y, a1.z+u1.z, a1.w+u1.w,
                    w0.x, w0.y, w0.z, w0.w, w1.x, w1.y, w1.z, w1.w};
    ull acc[8];
    #pragma unroll
    for (int ko=0;ko<8;++ko) acc[ko]=0ull;
    #pragma unroll
    for (int j=0;j<16;++j){
        ull vj = pk2(xc[j], xc[j]);
        #pragma unroll
        for (int ko=0;ko<8;++ko) ffma2(acc[ko], vj, f[j*8+ko]);
    }
    float* po = (oext ? oext : (g_xs + ooff)) + bt*2*CKD + c*8;
    float2 r0=up2(acc[0]), r1=up2(acc[1]), r2=up2(acc[2]), r3=up2(acc[3]);
    float2 r4=up2(acc[4]), r5=up2(acc[5]), r6=up2(acc[6]), r7=up2(acc[7]);
    *(float4*)po         = make_float4(r0.x,r1.x,r2.x,r3.x);   // even row 2t
    *(float4*)(po+4)     = make_float4(r4.x,r5.x,r6.x,r7.x);
    *(float4*)(po+CKD)   = make_float4(r0.y,r1.y,r2.y,r3.y);   // odd row 2t+1
    *(float4*)(po+CKD+4) = make_float4(r4.y,r5.y,r6.y,r7.y);
}

// ---------------- forward truncated DFT (unnormalized) ----------------
// srcsel: 0 = g_d, 1 = g_xs+voff. dstsel: 0 = g_part, 1 = g_ftd, 2 = g_ftx.
__global__ void __launch_bounds__(128) k_fdft(int srcsel, long voff, int dstsel,
        int n, int l, int stride){
    __shared__ ull stw[16*128];
    int ck = threadIdx.x;
    int m0 = blockIdx.x * 16;
    int b  = blockIdx.z;
    int chunk = n / gridDim.y;
    int s0 = blockIdx.y * chunk;
    const float* v  = srcsel ? (g_xs + voff) : g_d;
    const float* vb = v + (long)b*n*CKD + ck;
    ull acc[16];
    #pragma unroll
    for (int i=0;i<16;++i) acc[i]=0ull;
    for (int sb=0; sb<chunk; sb+=128){
        int tile = chunk - sb; if (tile > 128) tile = 128;
        #pragma unroll
        for (int ml=0; ml<16; ++ml){
            int m = m0 + ml;
            float2 val = make_float2(0.f, 0.f);
            if (m < l && ck < tile){
                int r = (m * (s0+sb+ck) * stride) & 4095;
                val = g_tw[r];
            }
            stw[ml*128 + ck] = pk2(val.x, val.y);
        }
        __syncthreads();
        if (tile == 128){
            #pragma unroll 4
            for (int sl=0; sl<128; ++sl){
                float xv = vb[(long)(s0+sb+sl)*CKD];
                ull xx = pk2(xv, xv);
                #pragma unroll
                for (int ml=0; ml<16; ++ml) ffma2(acc[ml], xx, stw[ml*128+sl]);
            }
        } else {
            for (int sl=0; sl<tile; ++sl){
                float xv = vb[(long)(s0+sb+sl)*CKD];
                ull xx = pk2(xv, xv);
                #pragma unroll
                for (int ml=0; ml<16; ++ml) ffma2(acc[ml], xx, stw[ml*128+sl]);
            }
        }
        __syncthreads();
    }
    float2* dst = (dstsel==0) ? g_part : ((dstsel==1) ? g_ftd : g_ftx);
    long ob = ((long)(blockIdx.y*16 + b)*64)*CKD + ck;
    #pragma unroll
    for (int ml=0; ml<16; ++ml){
        int m = m0 + ml;
        if (m < l) dst[ob + (long)m*CKD] = up2(acc[ml]);
    }
}

// ---------------- reduce s-split partials ----------------
__global__ void k_ftred(int which, int l, int ssp){
    long idx = blockIdx.x*(long)blockDim.x + threadIdx.x;
    if (idx >= (long)16*l*CKD) return;
    int ck = (int)(idx & 127);
    long r = idx >> 7;
    int m = (int)(r % l);
    int b = (int)(r / l);
    float2 a = make_float2(0.f, 0.f);
    for (int sp=0; sp<ssp; ++sp){
        float2 p = g_part[((long)(sp*16+b)*64 + m)*CKD + ck];
        a.x += p.x; a.y += p.y;
    }
    ((which==1) ? g_ftd : g_ftx)[((long)b*64 + m)*CKD + ck] = a;
}

// ---------------- mode mixing: oud = ftd*A + ftx*B ; ous = ftd*C ----------------
__global__ void __launch_bounds__(128) k_mix(int l){
    int m = blockIdx.x;
    int kind = blockIdx.y;     // 0: ud, 1: us
    int o = threadIdx.x;
    __shared__ ull sa[2][8][128], sb2[2][8][128];
    const float2* w0 = g_wt + ((long)(kind ? 2 : 0)*64 + m)*16384;
    const float2* w1 = g_wt + ((long)64 + m)*16384;   // B, kind0 only
    ull acc[16];
    #pragma unroll
    for (int i=0;i<16;++i) acc[i]=0ull;
    for (int half=0; half<2; ++half){
        #pragma unroll
        for (int bb=0; bb<8; ++bb){
            float2 f = g_ftd[((long)(half*8+bb)*64 + m)*CKD + o];
            sa [0][bb][o] = pk2(f.x, f.x);
            sb2[0][bb][o] = pk2(-f.y, f.y);
            if (!kind){
                float2 g = g_ftx[((long)(half*8+bb)*64 + m)*CKD + o];
                sa [1][bb][o] = pk2(g.x, g.x);
                sb2[1][bb][o] = pk2(-g.y, g.y);
            }
        }
        __syncthreads();
        #pragma unroll 2
        for (int i=0; i<128; ++i){
            float2 w = w0[(long)i*128 + o];
            ull wp = pk2(w.x, w.y), ws = pk2(w.y, w.x);
            ull vp = 0ull, vs = 0ull;
            if (!kind){
                float2 u = w1[(long)i*128 + o];
                vp = pk2(u.x, u.y); vs = pk2(u.y, u.x);
            }
            #pragma unroll
            for (int bb=0; bb<8; ++bb){
                ffma2(acc[half*8+bb], sa [0][bb][i], wp);
                ffma2(acc[half*8+bb], sb2[0][bb][i], ws);
                if (!kind){
                    ffma2(acc[half*8+bb], sa [1][bb][i], vp);
                    ffma2(acc[half*8+bb], sb2[1][bb][i], vs);
                }
            }
        }
        __syncthreads();
    }
    float2* dst = kind ? g_ous : g_oud;
    #pragma unroll
    for (int b=0; b<16; ++b) dst[((long)b*64 + m)*CKD + o] = up2(acc[b]);
}

// ---------------- inverse truncated DFT for both ud and us ----------------
__global__ void __launch_bounds__(128) k_idft(long uoff, int n, int l, int stride, float invn){
    __shared__ ull sa[64*16], sb[64*16];
    int ck = threadIdx.x;
    int b  = blockIdx.y;
    int tb = blockIdx.x * 32;
    for (int j=ck; j<l*16; j+=128){
        int m = j >> 4, tp = j & 15;
        int t0 = tb + 2*tp;
        float c = (m==0 || 2*m==n) ? 1.f : 2.f;
        float s = c * invn;
        float2 e0 = make_float2(0.f,0.f), e1 = make_float2(0.f,0.f);
        if (t0 < n){
            e0 = g_tw[(m*t0*stride) & 4095];
            if (t0+1 < n) e1 = g_tw[(m*(t0+1)*stride) & 4095];
        }
        sa[j] = pk2(s*e0.x, s*e1.x);
        sb[j] = pk2(s*e0.y, s*e1.y);
    }
    __syncthreads();
    ull au[16], av[16];
    #pragma unroll
    for (int i=0;i<16;++i){ au[i]=0ull; av[i]=0ull; }
    #pragma unroll 2
    for (int m=0; m<l; ++m){
        float2 yd = g_oud[((long)b*64 + m)*CKD + ck];
        float2 ys = g_ous[((long)b*64 + m)*CKD + ck];
        ull ydr = pk2(yd.x, yd.x), ydi = pk2(yd.y, yd.y);
        ull ysr = pk2(ys.x, ys.x), ysi = pk2(ys.y, ys.y);
        #pragma unroll
        for (int tp=0; tp<16; ++tp){
            ull a = sa[m*16+tp], bb = sb[m*16+tp];
            ffma2(au[tp], ydr, a); ffma2(au[tp], ydi, bb);
            ffma2(av[tp], ysr, a); ffma2(av[tp], ysi, bb);
        }
    }
    float* pud = g_ud + uoff + (long)b*n*CKD + ck;
    float* pus = g_us + uoff + (long)b*n*CKD + ck;
    #pragma unroll
    for (int tp=0; tp<16; ++tp){
        int t0 = tb + 2*tp;
        if (t0 < n){
            float2 u = up2(au[tp]), v = up2(av[tp]);
            pud[(long)t0*CKD] = u.x;
            pus[(long)t0*CKD] = v.x;
            if (t0+1 < n){
                pud[(long)(t0+1)*CKD] = u.y;
                pus[(long)(t0+1)*CKD] = v.y;
            }
        }
    }
}

// ---------------- LayerNorm + exact GELU in-place on (16,1,128) ----------------
__global__ void k_lngelu(const float* __restrict__ w, const float* __restrict__ bia, long off){
    int b = blockIdx.x, t = threadIdx.x;
    __shared__ float rs[8];
    float v = g_xs[off + (long)b*CKD + t];
    float s1 = v, s2 = v*v;
    #pragma unroll
    for (int o=16; o; o>>=1){
        s1 += __shfl_xor_sync(0xffffffffu, s1, o);
        s2 += __shfl_xor_sync(0xffffffffu, s2, o);
    }
    if ((t & 31) == 0){ rs[t>>5] = s1; rs[4+(t>>5)] = s2; }
    __syncthreads();
    float m1 = (rs[0]+rs[1]+rs[2]+rs[3]) * (1.0f/128.0f);
    float m2 = (rs[4]+rs[5]+rs[6]+rs[7]) * (1.0f/128.0f);
    float var = m2 - m1*m1;
    float xn = (v - m1) * rsqrtf(var + 1e-5f) * w[t] + bia[t];
    float ge = 0.5f * xn * (1.0f + erff(xn * 0.70710678118654752f));
    g_xs[off + (long)b*CKD + t] = ge;
}

// ---------------- host ----------------
extern "C" void kernel_launch(void* const* d_in, const int* in_sizes, int n_in,
                              void* d_out, int out_size) {
    const float* x   = (const float*)d_in[0];
    const float* Awr = (const float*)d_in[1];
    const float* Awi = (const float*)d_in[2];
    const float* Bwr = (const float*)d_in[3];
    const float* Bwi = (const float*)d_in[4];
    const float* Cwr = (const float*)d_in[5];
    const float* Cwi = (const float*)d_in[6];
    const float* lnw = (const float*)d_in[7];
    const float* lnb = (const float*)d_in[8];
    const float* ecs = (const float*)d_in[9];
    const float* ecd = (const float*)d_in[10];
    const float* rce = (const float*)d_in[11];
    const float* rco = (const float*)d_in[12];
    float* out = (float*)d_out;

    static const int NH[13]  = {4096,2048,1024,512,256,128,64,32,16,8,4,2,1};
    static const int LM[13]  = {64,64,64,64,64,64,33,17,9,5,3,2,1};
    static const int SSP[13] = {8,8,4,4,2,1,1,1,1,1,1,1,1};
    long OFF[13];
    OFF[0] = 0;
    for (int l=1; l<13; ++l) OFF[l] = OFF[l-1] + (long)16*NH[l-1]*128;

    k_base<<<16, 256>>>();
    long wblk = ((long)64*128*128 + 255) / 256;
    k_wtrans<<<(unsigned)wblk, 256>>>(Awr, Awi, 0);
    k_wtrans<<<(unsigned)wblk, 256>>>(Bwr, Bwi, 1);
    k_wtrans<<<(unsigned)wblk, 256>>>(Cwr, Cwi, 2);

    for (int l=0; l<13; ++l){
        int nh = NH[l], lm = LM[l], ssp = SSP[l], stride = 4096 / nh;
        long nthr = (long)16*nh*16;
        unsigned blk = (unsigned)((nthr + 255) / 256);
        k_decompose<<<blk, 256>>>(l==0 ? x : (const float*)0, l ? OFF[l-1] : 0,
                                  OFF[l], ecs, ecd, nh);
        dim3 gf((lm+15)/16, ssp, 16);
        k_fdft<<<gf, 128>>>(0, 0,      ssp>1 ? 0 : 1, nh, lm, stride);     // d -> ftd
        if (ssp > 1){
            unsigned rb = (unsigned)(((long)16*lm*128 + 255)/256);
            k_ftred<<<rb, 256>>>(1, lm, ssp);
        }
        k_fdft<<<gf, 128>>>(1, OFF[l], ssp>1 ? 0 : 2, nh, lm, stride);     // s -> ftx
        if (ssp > 1){
            unsigned rb = (unsigned)(((long)16*lm*128 + 255)/256);
            k_ftred<<<rb, 256>>>(2, lm, ssp);
        }
        k_mix<<<dim3(lm, 2), 128>>>(lm);
        k_idft<<<dim3((nh+31)/32, 16), 128>>>(OFF[l], nh, lm, stride, 1.0f/(float)nh);
    }

    k_lngelu<<<16, 128>>>(lnw, lnb, OFF[12]);

    for (int l=12; l>=0; --l){
        int nh = NH[l];
        long nthr = (long)16*nh*16;
        unsigned blk = (unsigned)((nthr + 255) / 256);
        k_recon<<<blk, 256>>>(OFF[l], OFF[l],
                              l ? (float*)0 : out, l ? OFF[l-1] : 0,
                              rce, rco, nh);
    }
}

// round 3
// speedup vs baseline: 1.2443x; 1.2443x over previous
#include <cuda_runtime.h>
#include <cuda_bf16.h>

#define CKD 128
typedef unsigned long long ull;

// ---------------- static scratch ----------------
__device__ float  g_xs[(long)16*8191*128];
__device__ float  g_d [(long)16*4096*128];
__device__ float  g_ud[(long)16*8191*128];
__device__ float  g_us[(long)16*8191*128];
__device__ float2 g_part[(long)16*16*64*128];
__device__ float2 g_ftd[16*64*128];
__device__ float2 g_ftx[16*64*128];
__device__ float2 g_oud[16*64*128];
__device__ float2 g_ous[16*64*128];
__device__ float2 g_wt[(long)3*64*128*128];
__device__ float2 g_tw[4096+64];

// ---------------- f32x2 helpers ----------------
__device__ __forceinline__ ull pk2(float x, float y){
    ull r; asm("mov.b64 %0, {%1, %2};" : "=l"(r) : "f"(x), "f"(y)); return r;
}
__device__ __forceinline__ float2 up2(ull v){
    float2 r; asm("mov.b64 {%0, %1}, %2;" : "=f"(r.x), "=f"(r.y) : "l"(v)); return r;
}
__device__ __forceinline__ void ffma2(ull &acc, ull a, ull b){
    asm("fma.rn.f32x2 %0, %1, %2, %0;" : "+l"(acc) : "l"(a), "l"(b));
}

// ---------------- base twiddle table: g_tw[r] = (cos(2*pi*r/4096), -sin(...)) ----------------
__global__ void k_base(){
    int r = blockIdx.x*blockDim.x + threadIdx.x;
    if (r >= 4096) return;
    float s, c;
    sincospif(r/2048.0f, &s, &c);
    g_tw[r] = make_float2(c, -s);
    if (r < 64) g_tw[4096+r] = make_float2(0.f, 0.f);
}

// ---------------- weight transpose (i,o,m) -> (m,i,o) complex ----------------
__global__ void k_wtrans(const float* __restrict__ wr, const float* __restrict__ wi, int mat){
    long idx = blockIdx.x*(long)blockDim.x + threadIdx.x;
    if (idx >= (long)64*128*128) return;
    int m = (int)(idx & 63);
    int o = (int)((idx >> 6) & 127);
    int i = (int)(idx >> 13);
    g_wt[((long)mat*64 + m)*16384 + (long)i*128 + o] = make_float2(wr[idx], wi[idx]);
}

// ---------------- wavelet decompose ----------------
__global__ void __launch_bounds__(256) k_decompose(const float* __restrict__ xext, long xoff,
        long soff, const float* __restrict__ ecs, const float* __restrict__ ecd, int nh){
    __shared__ ull f[128];
    if (threadIdx.x < 128) f[threadIdx.x] = pk2(ecs[threadIdx.x], ecd[threadIdx.x]);
    __syncthreads();
    long idx = blockIdx.x*(long)blockDim.x + threadIdx.x;
    if (idx >= (long)16*nh*16) return;
    int c = (int)(idx & 15);
    long bt = idx >> 4;
    const float* xin = xext ? xext : (g_xs + xoff);
    const float* pe = xin + bt*2*CKD + c*8;
    float4 e0 = *(const float4*)(pe);
    float4 e1 = *(const float4*)(pe+4);
    float4 o0 = *(const float4*)(pe+CKD);
    float4 o1 = *(const float4*)(pe+CKD+4);
    float xa[16] = {e0.x,e0.y,e0.z,e0.w, e1.x,e1.y,e1.z,e1.w,
                    o0.x,o0.y,o0.z,o0.w, o1.x,o1.y,o1.z,o1.w};
    ull acc[8];
    #pragma unroll
    for (int ko=0;ko<8;++ko) acc[ko]=0ull;
    #pragma unroll
    for (int j=0;j<16;++j){
        ull vj = pk2(xa[j], xa[j]);
        #pragma unroll
        for (int ko=0;ko<8;++ko) ffma2(acc[ko], vj, f[j*8+ko]);
    }
    float* ps = g_xs + soff + bt*CKD + c*8;
    float* pd = g_d         + bt*CKD + c*8;
    float2 r0=up2(acc[0]), r1=up2(acc[1]), r2=up2(acc[2]), r3=up2(acc[3]);
    float2 r4=up2(acc[4]), r5=up2(acc[5]), r6=up2(acc[6]), r7=up2(acc[7]);
    *(float4*)ps     = make_float4(r0.x,r1.x,r2.x,r3.x);
    *(float4*)(ps+4) = make_float4(r4.x,r5.x,r6.x,r7.x);
    *(float4*)pd     = make_float4(r0.y,r1.y,r2.y,r3.y);
    *(float4*)(pd+4) = make_float4(r4.y,r5.y,r6.y,r7.y);
}

// ---------------- reconstruction ----------------
__global__ void __launch_bounds__(256) k_recon(long xoff, long uoff,
        float* __restrict__ oext, long ooff,
        const float* __restrict__ rce, const float* __restrict__ rco, int nh){
    __shared__ ull f[128];
    if (threadIdx.x < 128) f[threadIdx.x] = pk2(rce[threadIdx.x], rco[threadIdx.x]);
    __syncthreads();
    long idx = blockIdx.x*(long)blockDim.x + threadIdx.x;
    if (idx >= (long)16*nh*16) return;
    int c = (int)(idx & 15);
    long bt = idx >> 4;
    const float* px = g_xs + xoff + bt*CKD + c*8;
    const float* pu = g_us + uoff + bt*CKD + c*8;
    const float* pw = g_ud + uoff + bt*CKD + c*8;
    float4 a0 = *(const float4*)px,     u0 = *(const float4*)pu;
    float4 a1 = *(const float4*)(px+4), u1 = *(const float4*)(pu+4);
    float4 w0 = *(const float4*)pw,     w1 = *(const float4*)(pw+4);
    float xc[16] = {a0.x+u0.x, a0.y+u0.y, a0.z+u0.z, a0.w+u0.w,
                    a1.x+u1.x, a1.y+u1.y, a1.z+u1.z, a1.w+u1.w,
                    w0.x, w0.y, w0.z, w0.w, w1.x, w1.y, w1.z, w1.w};
    ull acc[8];
    #pragma unroll
    for (int ko=0;ko<8;++ko) acc[ko]=0ull;
    #pragma unroll
    for (int j=0;j<16;++j){
        ull vj = pk2(xc[j], xc[j]);
        #pragma unroll
        for (int ko=0;ko<8;++ko) ffma2(acc[ko], vj, f[j*8+ko]);
    }
    float* po = (oext ? oext : (g_xs + ooff)) + bt*2*CKD + c*8;
    float2 r0=up2(acc[0]), r1=up2(acc[1]), r2=up2(acc[2]), r3=up2(acc[3]);
    float2 r4=up2(acc[4]), r5=up2(acc[5]), r6=up2(acc[6]), r7=up2(acc[7]);
    *(float4*)po         = make_float4(r0.x,r1.x,r2.x,r3.x);
    *(float4*)(po+4)     = make_float4(r4.x,r5.x,r6.x,r7.x);
    *(float4*)(po+CKD)   = make_float4(r0.y,r1.y,r2.y,r3.y);
    *(float4*)(po+CKD+4) = make_float4(r4.y,r5.y,r6.y,r7.y);
}

// ---------------- folded forward truncated DFT ----------------
// fold: even m use (v[s]+v[s+n/2]), odd m use (v[s]-v[s+n/2]), s < n/2.
// block: 128 ck threads, 16 modes, 2 batches (blockIdx.z -> b0=2z, b1=2z+1).
__global__ void __launch_bounds__(128) k_fdft(int srcsel, long voff, int dstsel,
        int n, int l, int stride){
    __shared__ ulonglong2 stw[64*8];
    int ck = threadIdx.x;
    int m0 = blockIdx.x * 16;
    int bz = blockIdx.z;
    int b0 = 2*bz, b1 = 2*bz+1;
    int n2 = n >> 1;
    const float* src = srcsel ? (g_xs + voff) : g_d;
    float2* dst = (dstsel==0) ? g_part : ((dstsel==1) ? g_ftd : g_ftx);

    if (n2 == 0){   // n==1: Y0 = v
        if (m0 == 0){
            float v0 = src[(long)b0*CKD + ck];
            float v1 = src[(long)b1*CKD + ck];
            dst[((long)b0*64)*CKD + ck] = make_float2(v0, 0.f);
            dst[((long)b1*64)*CKD + ck] = make_float2(v1, 0.f);
        }
        return;
    }
    int chunk = n2 / gridDim.y;
    int s0 = blockIdx.y * chunk;
    const float* p0 = src + ((long)b0*n)*CKD + ck;
    const float* p1 = src + ((long)b1*n)*CKD + ck;
    ull acc[16][2];
    #pragma unroll
    for (int i=0;i<16;++i){ acc[i][0]=0ull; acc[i][1]=0ull; }

    for (int sb=0; sb<chunk; sb+=64){
        int tile = chunk - sb; if (tile > 64) tile = 64;
        for (int q = ck; q < 64*8; q += 128){
            int sl = q >> 3, j = q & 7;
            int me = m0 + 2*j, mo = me + 1;
            float2 te = make_float2(0.f,0.f), to = make_float2(0.f,0.f);
            if (sl < tile){
                int s = s0 + sb + sl;
                if (me < l) te = g_tw[(me*s*stride) & 4095];
                if (mo < l) to = g_tw[(mo*s*stride) & 4095];
            }
            stw[q] = make_ulonglong2(pk2(te.x,te.y), pk2(to.x,to.y));
        }
        __syncthreads();
        #pragma unroll 2
        for (int sl=0; sl<tile; ++sl){
            long so = (long)(s0+sb+sl)*CKD;
            float v00 = p0[so], v01 = p0[so + (long)n2*CKD];
            float v10 = p1[so], v11 = p1[so + (long)n2*CKD];
            ull a0  = pk2(v00+v01, v00+v01);
            ull d0  = pk2(v00-v01, v00-v01);
            ull a1  = pk2(v10+v11, v10+v11);
            ull d1  = pk2(v10-v11, v10-v11);
            const ulonglong2* row = &stw[sl*8];
            #pragma unroll
            for (int j=0;j<8;++j){
                ulonglong2 t = row[j];
                ffma2(acc[2*j][0],   a0, t.x);
                ffma2(acc[2*j][1],   a1, t.x);
                ffma2(acc[2*j+1][0], d0, t.y);
                ffma2(acc[2*j+1][1], d1, t.y);
            }
        }
        __syncthreads();
    }
    long ob0 = ((long)(blockIdx.y*16 + b0)*64)*CKD + ck;
    long ob1 = ((long)(blockIdx.y*16 + b1)*64)*CKD + ck;
    #pragma unroll
    for (int ml=0; ml<16; ++ml){
        int m = m0 + ml;
        if (m < l){
            dst[ob0 + (long)m*CKD] = up2(acc[ml][0]);
            dst[ob1 + (long)m*CKD] = up2(acc[ml][1]);
        }
    }
}

// ---------------- reduce s-split partials ----------------
__global__ void k_ftred(int which, int l, int ssp){
    long idx = blockIdx.x*(long)blockDim.x + threadIdx.x;
    if (idx >= (long)16*l*CKD) return;
    int ck = (int)(idx & 127);
    long r = idx >> 7;
    int m = (int)(r % l);
    int b = (int)(r / l);
    float2 a = make_float2(0.f, 0.f);
    for (int sp=0; sp<ssp; ++sp){
        float2 p = g_part[((long)(sp*16+b)*64 + m)*CKD + ck];
        a.x += p.x; a.y += p.y;
    }
    ((which==1) ? g_ftd : g_ftx)[((long)b*64 + m)*CKD + ck] = a;
}

// ---------------- merged mode mixing: oud = ftd*A + ftx*B ; ous = ftd*C ----------------
// grid (lm, 4): blockIdx.y selects 4 batches.
__global__ void __launch_bounds__(128) k_mix(int l){
    __shared__ __align__(16) ull sda[128*4], sdb[128*4], sxa[128*4], sxb[128*4];
    int o = threadIdx.x;
    int m = blockIdx.x;
    int bg = blockIdx.y;
    #pragma unroll
    for (int j=0;j<4;++j){
        float2 f = g_ftd[((long)(bg*4+j)*64 + m)*CKD + o];
        sda[o*4+j] = pk2(f.x, f.x);
        sdb[o*4+j] = pk2(-f.y, f.y);
        float2 g = g_ftx[((long)(bg*4+j)*64 + m)*CKD + o];
        sxa[o*4+j] = pk2(g.x, g.x);
        sxb[o*4+j] = pk2(-g.y, g.y);
    }
    __syncthreads();
    const float2* wA = g_wt + (long)m*16384 + o;
    const float2* wB = wA + (long)64*16384;
    const float2* wC = wB + (long)64*16384;
    ull ud[4], us[4];
    #pragma unroll
    for (int j=0;j<4;++j){ ud[j]=0ull; us[j]=0ull; }
    #pragma unroll 2
    for (int i=0;i<128;++i){
        float2 a = wA[(long)i*CKD];
        float2 b = wB[(long)i*CKD];
        float2 c = wC[(long)i*CKD];
        ull Ap = pk2(a.x, a.y), As = pk2(a.y, a.x);
        ull Bp = pk2(b.x, b.y), Bs = pk2(b.y, b.x);
        ull Cp = pk2(c.x, c.y), Cs = pk2(c.y, c.x);
        ulonglong2 d01 = *(const ulonglong2*)&sda[i*4];
        ulonglong2 d23 = *(const ulonglong2*)&sda[i*4+2];
        ulonglong2 e01 = *(const ulonglong2*)&sdb[i*4];
        ulonglong2 e23 = *(const ulonglong2*)&sdb[i*4+2];
        ulonglong2 x01 = *(const ulonglong2*)&sxa[i*4];
        ulonglong2 x23 = *(const ulonglong2*)&sxa[i*4+2];
        ulonglong2 y01 = *(const ulonglong2*)&sxb[i*4];
        ulonglong2 y23 = *(const ulonglong2*)&sxb[i*4+2];
        ffma2(ud[0], d01.x, Ap); ffma2(ud[0], e01.x, As);
        ffma2(ud[0], x01.x, Bp); ffma2(ud[0], y01.x, Bs);
        ffma2(us[0], d01.x, Cp); ffma2(us[0], e01.x, Cs);
        ffma2(ud[1], d01.y, Ap); ffma2(ud[1], e01.y, As);
        ffma2(ud[1], x01.y, Bp); ffma2(ud[1], y01.y, Bs);
        ffma2(us[1], d01.y, Cp); ffma2(us[1], e01.y, Cs);
        ffma2(ud[2], d23.x, Ap); ffma2(ud[2], e23.x, As);
        ffma2(ud[2], x23.x, Bp); ffma2(ud[2], y23.x, Bs);
        ffma2(us[2], d23.x, Cp); ffma2(us[2], e23.x, Cs);
        ffma2(ud[3], d23.y, Ap); ffma2(ud[3], e23.y, As);
        ffma2(ud[3], x23.y, Bp); ffma2(ud[3], y23.y, Bs);
        ffma2(us[3], d23.y, Cp); ffma2(us[3], e23.y, Cs);
    }
    #pragma unroll
    for (int j=0;j<4;++j){
        g_oud[((long)(bg*4+j)*64 + m)*CKD + o] = up2(ud[j]);
        g_ous[((long)(bg*4+j)*64 + m)*CKD + o] = up2(us[j]);
    }
}

// ---------------- folded inverse truncated DFT (both ud and us packed) ----------------
// out[t'] = E+O, out[t'+n/2] = E-O; E/O split by mode parity. Lanes pack (ud,us).
__global__ void __launch_bounds__(128) k_idft(long uoff, int n, int l, int stride, float invn){
    __shared__ ulonglong2 tab[64*16];
    int ck = threadIdx.x;
    int b  = blockIdx.y;
    int n2 = n >> 1;
    if (n2 == 0){   // n==1: out = Y0.re
        float2 yd = g_oud[(long)b*64*CKD + ck];
        float2 ys = g_ous[(long)b*64*CKD + ck];
        g_ud[uoff + (long)b*CKD + ck] = yd.x;
        g_us[uoff + (long)b*CKD + ck] = ys.x;
        return;
    }
    int tb = blockIdx.x * 16;
    for (int q = ck; q < l*16; q += 128){
        int m = q >> 4, tp = q & 15;
        int t = tb + tp;
        float2 e = make_float2(0.f, 0.f);
        float sc = 0.f;
        if (t < n2){
            e = g_tw[(m*t*stride) & 4095];
            sc = ((m==0) || (2*m==n)) ? invn : 2.f*invn;
        }
        tab[q] = make_ulonglong2(pk2(sc*e.x, sc*e.x), pk2(sc*e.y, sc*e.y));
    }
    __syncthreads();
    ull accE[16], accO[16];
    #pragma unroll
    for (int i=0;i<16;++i){ accE[i]=0ull; accO[i]=0ull; }
    const float2* pod = g_oud + (long)b*64*CKD + ck;
    const float2* pos = g_ous + (long)b*64*CKD + ck;
    for (int m = 0; m < l; m += 2){
        {
            float2 yd = pod[(long)m*CKD];
            float2 ys = pos[(long)m*CKD];
            ull re2 = pk2(yd.x, ys.x);
            ull im2 = pk2(yd.y, ys.y);
            const ulonglong2* row = &tab[m*16];
            #pragma unroll
            for (int tp=0; tp<16; ++tp){
                ulonglong2 t = row[tp];
                ffma2(accE[tp], re2, t.x);
                ffma2(accE[tp], im2, t.y);
            }
        }
        if (m+1 < l){
            float2 yd = pod[(long)(m+1)*CKD];
            float2 ys = pos[(long)(m+1)*CKD];
            ull re2 = pk2(yd.x, ys.x);
            ull im2 = pk2(yd.y, ys.y);
            const ulonglong2* row = &tab[(m+1)*16];
            #pragma unroll
            for (int tp=0; tp<16; ++tp){
                ulonglong2 t = row[tp];
                ffma2(accO[tp], re2, t.x);
                ffma2(accO[tp], im2, t.y);
            }
        }
    }
    float* pud = g_ud + uoff + (long)b*n*CKD + ck;
    float* pus = g_us + uoff + (long)b*n*CKD + ck;
    #pragma unroll
    for (int tp=0; tp<16; ++tp){
        int t = tb + tp;
        if (t < n2){
            float2 E = up2(accE[tp]), O = up2(accO[tp]);
            pud[(long)t*CKD]      = E.x + O.x;
            pus[(long)t*CKD]      = E.y + O.y;
            pud[(long)(t+n2)*CKD] = E.x - O.x;
            pus[(long)(t+n2)*CKD] = E.y - O.y;
        }
    }
}

// ---------------- LayerNorm + exact GELU in-place on (16,1,128) ----------------
__global__ void k_lngelu(const float* __restrict__ w, const float* __restrict__ bia, long off){
    int b = blockIdx.x, t = threadIdx.x;
    __shared__ float rs[8];
    float v = g_xs[off + (long)b*CKD + t];
    float s1 = v, s2 = v*v;
    #pragma unroll
    for (int o=16; o; o>>=1){
        s1 += __shfl_xor_sync(0xffffffffu, s1, o);
        s2 += __shfl_xor_sync(0xffffffffu, s2, o);
    }
    if ((t & 31) == 0){ rs[t>>5] = s1; rs[4+(t>>5)] = s2; }
    __syncthreads();
    float m1 = (rs[0]+rs[1]+rs[2]+rs[3]) * (1.0f/128.0f);
    float m2 = (rs[4]+rs[5]+rs[6]+rs[7]) * (1.0f/128.0f);
    float var = m2 - m1*m1;
    float xn = (v - m1) * rsqrtf(var + 1e-5f) * w[t] + bia[t];
    float ge = 0.5f * xn * (1.0f + erff(xn * 0.70710678118654752f));
    g_xs[off + (long)b*CKD + t] = ge;
}

// ---------------- host ----------------
extern "C" void kernel_launch(void* const* d_in, const int* in_sizes, int n_in,
                              void* d_out, int out_size) {
    const float* x   = (const float*)d_in[0];
    const float* Awr = (const float*)d_in[1];
    const float* Awi = (const float*)d_in[2];
    const float* Bwr = (const float*)d_in[3];
    const float* Bwi = (const float*)d_in[4];
    const float* Cwr = (const float*)d_in[5];
    const float* Cwi = (const float*)d_in[6];
    const float* lnw = (const float*)d_in[7];
    const float* lnb = (const float*)d_in[8];
    const float* ecs = (const float*)d_in[9];
    const float* ecd = (const float*)d_in[10];
    const float* rce = (const float*)d_in[11];
    const float* rco = (const float*)d_in[12];
    float* out = (float*)d_out;

    static const int NH[13]  = {4096,2048,1024,512,256,128,64,32,16,8,4,2,1};
    static const int LM[13]  = {64,64,64,64,64,64,33,17,9,5,3,2,1};
    static const int SSP[13] = {16,16,8,4,2,1,1,1,1,1,1,1,1};
    long OFF[13];
    OFF[0] = 0;
    for (int l=1; l<13; ++l) OFF[l] = OFF[l-1] + (long)16*NH[l-1]*128;

    k_base<<<16, 256>>>();
    long wblk = ((long)64*128*128 + 255) / 256;
    k_wtrans<<<(unsigned)wblk, 256>>>(Awr, Awi, 0);
    k_wtrans<<<(unsigned)wblk, 256>>>(Bwr, Bwi, 1);
    k_wtrans<<<(unsigned)wblk, 256>>>(Cwr, Cwi, 2);

    for (int l=0; l<13; ++l){
        int nh = NH[l], lm = LM[l], ssp = SSP[l], stride = 4096 / nh;
        long nthr = (long)16*nh*16;
        unsigned blk = (unsigned)((nthr + 255) / 256);
        k_decompose<<<blk, 256>>>(l==0 ? x : (const float*)0, l ? OFF[l-1] : 0,
                                  OFF[l], ecs, ecd, nh);
        dim3 gf((lm+15)/16, ssp, 8);
        k_fdft<<<gf, 128>>>(0, 0,      ssp>1 ? 0 : 1, nh, lm, stride);     // d -> ftd
        if (ssp > 1){
            unsigned rb = (unsigned)(((long)16*lm*128 + 255)/256);
            k_ftred<<<rb, 256>>>(1, lm, ssp);
        }
        k_fdft<<<gf, 128>>>(1, OFF[l], ssp>1 ? 0 : 2, nh, lm, stride);     // s -> ftx
        if (ssp > 1){
            unsigned rb = (unsigned)(((long)16*lm*128 + 255)/256);
            k_ftred<<<rb, 256>>>(2, lm, ssp);
        }
        k_mix<<<dim3(lm, 4), 128>>>(lm);
        int n2 = nh >> 1;
        int gx = (n2 == 0) ? 1 : (n2 + 15)/16;
        k_idft<<<dim3(gx, 16), 128>>>(OFF[l], nh, lm, stride, 1.0f/(float)nh);
    }

    k_lngelu<<<16, 128>>>(lnw, lnb, OFF[12]);

    for (int l=12; l>=0; --l){
        int nh = NH[l];
        long nthr = (long)16*nh*16;
        unsigned blk = (unsigned)((nthr + 255) / 256);
        k_recon<<<blk, 256>>>(OFF[l], OFF[l],
                              l ? (float*)0 : out, l ? OFF[l-1] : 0,
                              rce, rco, nh);
    }
}

// round 4
// speedup vs baseline: 1.6694x; 1.3416x over previous
#include <cuda_runtime.h>
#include <cuda_bf16.h>

#define CKD 128
typedef unsigned long long ull;

// ---------------- static scratch ----------------
__device__ float  g_xs[(long)16*8191*128];
__device__ float  g_d [(long)16*4096*128];
__device__ float  g_ud[(long)16*8191*128];
__device__ float  g_us[(long)16*8191*128];
__device__ float2 g_part[(long)2*16*16*64*128];
__device__ float2 g_ftd[16*64*128];
__device__ float2 g_ftx[16*64*128];
__device__ float2 g_oud[16*64*128];
__device__ float2 g_ous[16*64*128];
__device__ float2 g_wt[(long)3*64*128*128];
__device__ float2 g_tw[4096+64];

// ---------------- f32x2 helpers ----------------
__device__ __forceinline__ ull pk2(float x, float y){
    ull r; asm("mov.b64 %0, {%1, %2};" : "=l"(r) : "f"(x), "f"(y)); return r;
}
__device__ __forceinline__ float2 up2(ull v){
    float2 r; asm("mov.b64 {%0, %1}, %2;" : "=f"(r.x), "=f"(r.y) : "l"(v)); return r;
}
__device__ __forceinline__ void ffma2(ull &acc, ull a, ull b){
    asm("fma.rn.f32x2 %0, %1, %2, %0;" : "+l"(acc) : "l"(a), "l"(b));
}

// ---------------- base twiddle table ----------------
__global__ void k_base(){
    int r = blockIdx.x*blockDim.x + threadIdx.x;
    if (r >= 4096) return;
    float s, c;
    sincospif(r/2048.0f, &s, &c);
    g_tw[r] = make_float2(c, -s);
    if (r < 64) g_tw[4096+r] = make_float2(0.f, 0.f);
}

// ---------------- weight transpose (i,o,m) -> (m,i,o), all 3 matrices ----------------
__global__ void k_wtrans(const float* __restrict__ Ar, const float* __restrict__ Ai,
                         const float* __restrict__ Br, const float* __restrict__ Bi,
                         const float* __restrict__ Cr, const float* __restrict__ Ci){
    long gidx = blockIdx.x*(long)blockDim.x + threadIdx.x;
    const long per = (long)64*128*128;
    if (gidx >= 3*per) return;
    int mat = (int)(gidx / per);
    long idx = gidx - (long)mat*per;
    const float* wr = mat==0 ? Ar : (mat==1 ? Br : Cr);
    const float* wi = mat==0 ? Ai : (mat==1 ? Bi : Ci);
    int m = (int)(idx & 63);
    int o = (int)((idx >> 6) & 127);
    int i = (int)(idx >> 13);
    g_wt[((long)mat*64 + m)*16384 + (long)i*128 + o] = make_float2(wr[idx], wi[idx]);
}

// ---------------- wavelet decompose ----------------
__global__ void __launch_bounds__(256) k_decompose(const float* __restrict__ xext, long xoff,
        long soff, const float* __restrict__ ecs, const float* __restrict__ ecd, int nh){
    __shared__ ull f[128];
    if (threadIdx.x < 128) f[threadIdx.x] = pk2(ecs[threadIdx.x], ecd[threadIdx.x]);
    __syncthreads();
    long idx = blockIdx.x*(long)blockDim.x + threadIdx.x;
    if (idx >= (long)16*nh*16) return;
    int c = (int)(idx & 15);
    long bt = idx >> 4;
    const float* xin = xext ? xext : (g_xs + xoff);
    const float* pe = xin + bt*2*CKD + c*8;
    float4 e0 = *(const float4*)(pe);
    float4 e1 = *(const float4*)(pe+4);
    float4 o0 = *(const float4*)(pe+CKD);
    float4 o1 = *(const float4*)(pe+CKD+4);
    float xa[16] = {e0.x,e0.y,e0.z,e0.w, e1.x,e1.y,e1.z,e1.w,
                    o0.x,o0.y,o0.z,o0.w, o1.x,o1.y,o1.z,o1.w};
    ull acc[8];
    #pragma unroll
    for (int ko=0;ko<8;++ko) acc[ko]=0ull;
    #pragma unroll
    for (int j=0;j<16;++j){
        ull vj = pk2(xa[j], xa[j]);
        #pragma unroll
        for (int ko=0;ko<8;++ko) ffma2(acc[ko], vj, f[j*8+ko]);
    }
    float* ps = g_xs + soff + bt*CKD + c*8;
    float* pd = g_d         + bt*CKD + c*8;
    float2 r0=up2(acc[0]), r1=up2(acc[1]), r2=up2(acc[2]), r3=up2(acc[3]);
    float2 r4=up2(acc[4]), r5=up2(acc[5]), r6=up2(acc[6]), r7=up2(acc[7]);
    *(float4*)ps     = make_float4(r0.x,r1.x,r2.x,r3.x);
    *(float4*)(ps+4) = make_float4(r4.x,r5.x,r6.x,r7.x);
    *(float4*)pd     = make_float4(r0.y,r1.y,r2.y,r3.y);
    *(float4*)(pd+4) = make_float4(r4.y,r5.y,r6.y,r7.y);
}

// ---------------- reconstruction ----------------
__global__ void __launch_bounds__(256) k_recon(long xoff, long uoff,
        float* __restrict__ oext, long ooff,
        const float* __restrict__ rce, const float* __restrict__ rco, int nh){
    __shared__ ull f[128];
    if (threadIdx.x < 128) f[threadIdx.x] = pk2(rce[threadIdx.x], rco[threadIdx.x]);
    __syncthreads();
    long idx = blockIdx.x*(long)blockDim.x + threadIdx.x;
    if (idx >= (long)16*nh*16) return;
    int c = (int)(idx & 15);
    long bt = idx >> 4;
    const float* px = g_xs + xoff + bt*CKD + c*8;
    const float* pu = g_us + uoff + bt*CKD + c*8;
    const float* pw = g_ud + uoff + bt*CKD + c*8;
    float4 a0 = *(const float4*)px,     u0 = *(const float4*)pu;
    float4 a1 = *(const float4*)(px+4), u1 = *(const float4*)(pu+4);
    float4 w0 = *(const float4*)pw,     w1 = *(const float4*)(pw+4);
    float xc[16] = {a0.x+u0.x, a0.y+u0.y, a0.z+u0.z, a0.w+u0.w,
                    a1.x+u1.x, a1.y+u1.y, a1.z+u1.z, a1.w+u1.w,
                    w0.x, w0.y, w0.z, w0.w, w1.x, w1.y, w1.z, w1.w};
    ull acc[8];
    #pragma unroll
    for (int ko=0;ko<8;++ko) acc[ko]=0ull;
    #pragma unroll
    for (int j=0;j<16;++j){
        ull vj = pk2(xc[j], xc[j]);
        #pragma unroll
        for (int ko=0;ko<8;++ko) ffma2(acc[ko], vj, f[j*8+ko]);
    }
    float* po = (oext ? oext : (g_xs + ooff)) + bt*2*CKD + c*8;
    float2 r0=up2(acc[0]), r1=up2(acc[1]), r2=up2(acc[2]), r3=up2(acc[3]);
    float2 r4=up2(acc[4]), r5=up2(acc[5]), r6=up2(acc[6]), r7=up2(acc[7]);
    *(float4*)po         = make_float4(r0.x,r1.x,r2.x,r3.x);
    *(float4*)(po+4)     = make_float4(r4.x,r5.x,r6.x,r7.x);
    *(float4*)(po+CKD)   = make_float4(r0.y,r1.y,r2.y,r3.y);
    *(float4*)(po+CKD+4) = make_float4(r4.y,r5.y,r6.y,r7.y);
}

// ---------------- folded forward DFT, d & x fused, 16 modes, 1 batch / block ----------------
// grid: (ceil(l/16), ssp, 32). z = b + 16*src (src 0: g_d, 1: g_xs+voff).
__global__ void __launch_bounds__(128) k_fdft(long voff, int usepart,
        int n, int l, int stride){
    __shared__ ulonglong2 stw[64*8];
    int ck = threadIdx.x;
    int m0 = blockIdx.x * 16;
    int src = blockIdx.z >> 4;
    int b   = blockIdx.z & 15;
    int n2 = n >> 1;
    const float* vsrc = src ? (g_xs + voff) : g_d;
    float2* dstdir = src ? g_ftx : g_ftd;
    if (n2 == 0){   // n==1: Y0 = v
        if (m0 == 0){
            float v = vsrc[(long)b*CKD + ck];
            dstdir[((long)b*64)*CKD + ck] = make_float2(v, 0.f);
        }
        return;
    }
    int ssp = gridDim.y;
    int chunk = n2 / ssp;
    int s0 = blockIdx.y * chunk;
    const float* p = vsrc + ((long)b*n)*CKD + ck;
    ull acc[16];
    #pragma unroll
    for (int i=0;i<16;++i) acc[i]=0ull;
    for (int sb=0; sb<chunk; sb+=64){
        int tile = chunk - sb; if (tile > 64) tile = 64;
        for (int q = ck; q < 64*8; q += 128){
            int sl = q >> 3, j = q & 7;
            int me = m0 + 2*j, mo = me + 1;
            float2 te = make_float2(0.f,0.f), to = make_float2(0.f,0.f);
            if (sl < tile){
                int s = s0 + sb + sl;
                if (me < l) te = g_tw[(me*s*stride) & 4095];
                if (mo < l) to = g_tw[(mo*s*stride) & 4095];
            }
            stw[q] = make_ulonglong2(pk2(te.x,te.y), pk2(to.x,to.y));
        }
        __syncthreads();
        #pragma unroll 2
        for (int sl=0; sl<tile; ++sl){
            long so = (long)(s0+sb+sl)*CKD;
            float v0 = p[so], v1 = p[so + (long)n2*CKD];
            ull a = pk2(v0+v1, v0+v1);
            ull d = pk2(v0-v1, v0-v1);
            const ulonglong2* row = &stw[sl*8];
            #pragma unroll
            for (int j=0;j<8;++j){
                ulonglong2 t = row[j];
                ffma2(acc[2*j],   a, t.x);
                ffma2(acc[2*j+1], d, t.y);
            }
        }
        __syncthreads();
    }
    float2* dst = usepart
        ? (g_part + ((long)(src*ssp + blockIdx.y)*16 + b)*64*CKD)
        : (dstdir + (long)b*64*CKD);
    #pragma unroll
    for (int ml=0; ml<16; ++ml){
        int m = m0 + ml;
        if (m < l) dst[(long)m*CKD + ck] = up2(acc[ml]);
    }
}

// ---------------- reduce s-split partials (both arrays: blockIdx.y = src) ----------------
__global__ void k_ftred(int l, int ssp){
    long idx = blockIdx.x*(long)blockDim.x + threadIdx.x;
    if (idx >= (long)16*l*CKD) return;
    int src = blockIdx.y;
    int ck = (int)(idx & 127);
    long r = idx >> 7;
    int m = (int)(r % l);
    int b = (int)(r / l);
    float2 a = make_float2(0.f, 0.f);
    for (int sp=0; sp<ssp; ++sp){
        float2 p = g_part[((long)(src*ssp + sp)*16 + b)*64*CKD + (long)m*CKD + ck];
        a.x += p.x; a.y += p.y;
    }
    (src ? g_ftx : g_ftd)[((long)b*64 + m)*CKD + ck] = a;
}

// ---------------- merged mode mixing ----------------
__global__ void __launch_bounds__(128) k_mix(int l){
    __shared__ __align__(16) ull sda[128*4], sdb[128*4], sxa[128*4], sxb[128*4];
    int o = threadIdx.x;
    int m = blockIdx.x;
    int bg = blockIdx.y;
    #pragma unroll
    for (int j=0;j<4;++j){
        float2 f = g_ftd[((long)(bg*4+j)*64 + m)*CKD + o];
        sda[o*4+j] = pk2(f.x, f.x);
        sdb[o*4+j] = pk2(-f.y, f.y);
        float2 g = g_ftx[((long)(bg*4+j)*64 + m)*CKD + o];
        sxa[o*4+j] = pk2(g.x, g.x);
        sxb[o*4+j] = pk2(-g.y, g.y);
    }
    __syncthreads();
    const float2* wA = g_wt + (long)m*16384 + o;
    const float2* wB = wA + (long)64*16384;
    const float2* wC = wB + (long)64*16384;
    ull ud[4], us[4];
    #pragma unroll
    for (int j=0;j<4;++j){ ud[j]=0ull; us[j]=0ull; }
    #pragma unroll 2
    for (int i=0;i<128;++i){
        float2 a = wA[(long)i*CKD];
        float2 b = wB[(long)i*CKD];
        float2 c = wC[(long)i*CKD];
        ull Ap = pk2(a.x, a.y), As = pk2(a.y, a.x);
        ull Bp = pk2(b.x, b.y), Bs = pk2(b.y, b.x);
        ull Cp = pk2(c.x, c.y), Cs = pk2(c.y, c.x);
        ulonglong2 d01 = *(const ulonglong2*)&sda[i*4];
        ulonglong2 d23 = *(const ulonglong2*)&sda[i*4+2];
        ulonglong2 e01 = *(const ulonglong2*)&sdb[i*4];
        ulonglong2 e23 = *(const ulonglong2*)&sdb[i*4+2];
        ulonglong2 x01 = *(const ulonglong2*)&sxa[i*4];
        ulonglong2 x23 = *(const ulonglong2*)&sxa[i*4+2];
        ulonglong2 y01 = *(const ulonglong2*)&sxb[i*4];
        ulonglong2 y23 = *(const ulonglong2*)&sxb[i*4+2];
        ffma2(ud[0], d01.x, Ap); ffma2(ud[0], e01.x, As);
        ffma2(ud[0], x01.x, Bp); ffma2(ud[0], y01.x, Bs);
        ffma2(us[0], d01.x, Cp); ffma2(us[0], e01.x, Cs);
        ffma2(ud[1], d01.y, Ap); ffma2(ud[1], e01.y, As);
        ffma2(ud[1], x01.y, Bp); ffma2(ud[1], y01.y, Bs);
        ffma2(us[1], d01.y, Cp); ffma2(us[1], e01.y, Cs);
        ffma2(ud[2], d23.x, Ap); ffma2(ud[2], e23.x, As);
        ffma2(ud[2], x23.x, Bp); ffma2(ud[2], y23.x, Bs);
        ffma2(us[2], d23.x, Cp); ffma2(us[2], e23.x, Cs);
        ffma2(ud[3], d23.y, Ap); ffma2(ud[3], e23.y, As);
        ffma2(ud[3], x23.y, Bp); ffma2(ud[3], y23.y, Bs);
        ffma2(us[3], d23.y, Cp); ffma2(us[3], e23.y, Cs);
    }
    #pragma unroll
    for (int j=0;j<4;++j){
        g_oud[((long)(bg*4+j)*64 + m)*CKD + o] = up2(ud[j]);
        g_ous[((long)(bg*4+j)*64 + m)*CKD + o] = up2(us[j]);
    }
}

// ---------------- folded inverse DFT, two-pass (even/odd modes), (ud,us) lane-packed ----------------
__global__ void __launch_bounds__(128) k_idft(long uoff, int n, int l, int stride, float invn){
    __shared__ ulonglong2 tab[64*16];
    __shared__ ull stash[16*128];
    int ck = threadIdx.x;
    int b  = blockIdx.y;
    int n2 = n >> 1;
    if (n2 == 0){   // n==1: out = Y0.re
        float2 yd = g_oud[(long)b*64*CKD + ck];
        float2 ys = g_ous[(long)b*64*CKD + ck];
        g_ud[uoff + (long)b*CKD + ck] = yd.x;
        g_us[uoff + (long)b*CKD + ck] = ys.x;
        return;
    }
    int tb = blockIdx.x * 16;
    for (int q = ck; q < l*16; q += 128){
        int m = q >> 4, tp = q & 15;
        int t = tb + tp;
        float2 e = make_float2(0.f, 0.f);
        float sc = 0.f;
        if (t < n2){
            e = g_tw[(m*t*stride) & 4095];
            sc = ((m==0) || (2*m==n)) ? invn : 2.f*invn;
        }
        tab[q] = make_ulonglong2(pk2(sc*e.x, sc*e.x), pk2(sc*e.y, sc*e.y));
    }
    __syncthreads();
    const float2* pod = g_oud + (long)b*64*CKD + ck;
    const float2* pos = g_ous + (long)b*64*CKD + ck;
    ull acc[16];
    // pass 1: even modes -> accE
    #pragma unroll
    for (int i=0;i<16;++i) acc[i]=0ull;
    #pragma unroll 2
    for (int m=0; m<l; m+=2){
        float2 yd = pod[(long)m*CKD];
        float2 ys = pos[(long)m*CKD];
        ull re2 = pk2(yd.x, ys.x);
        ull im2 = pk2(yd.y, ys.y);
        const ulonglong2* row = &tab[m*16];
        #pragma unroll
        for (int tp=0; tp<16; ++tp){
            ulonglong2 t = row[tp];
            ffma2(acc[tp], re2, t.x);
            ffma2(acc[tp], im2, t.y);
        }
    }
    #pragma unroll
    for (int tp=0; tp<16; ++tp) stash[tp*128 + ck] = acc[tp];
    // pass 2: odd modes -> accO (reuse regs)
    #pragma unroll
    for (int i=0;i<16;++i) acc[i]=0ull;
    #pragma unroll 2
    for (int m=1; m<l; m+=2){
        float2 yd = pod[(long)m*CKD];
        float2 ys = pos[(long)m*CKD];
        ull re2 = pk2(yd.x, ys.x);
        ull im2 = pk2(yd.y, ys.y);
        const ulonglong2* row = &tab[m*16];
        #pragma unroll
        for (int tp=0; tp<16; ++tp){
            ulonglong2 t = row[tp];
            ffma2(acc[tp], re2, t.x);
            ffma2(acc[tp], im2, t.y);
        }
    }
    float* pud = g_ud + uoff + (long)b*n*CKD + ck;
    float* pus = g_us + uoff + (long)b*n*CKD + ck;
    #pragma unroll
    for (int tp=0; tp<16; ++tp){
        int t = tb + tp;
        if (t < n2){
            float2 E = up2(stash[tp*128 + ck]), O = up2(acc[tp]);
            pud[(long)t*CKD]      = E.x + O.x;
            pus[(long)t*CKD]      = E.y + O.y;
            pud[(long)(t+n2)*CKD] = E.x - O.x;
            pus[(long)(t+n2)*CKD] = E.y - O.y;
        }
    }
}

// ---------------- LayerNorm + exact GELU ----------------
__global__ void k_lngelu(const float* __restrict__ w, const float* __restrict__ bia, long off){
    int b = blockIdx.x, t = threadIdx.x;
    __shared__ float rs[8];
    float v = g_xs[off + (long)b*CKD + t];
    float s1 = v, s2 = v*v;
    #pragma unroll
    for (int o=16; o; o>>=1){
        s1 += __shfl_xor_sync(0xffffffffu, s1, o);
        s2 += __shfl_xor_sync(0xffffffffu, s2, o);
    }
    if ((t & 31) == 0){ rs[t>>5] = s1; rs[4+(t>>5)] = s2; }
    __syncthreads();
    float m1 = (rs[0]+rs[1]+rs[2]+rs[3]) * (1.0f/128.0f);
    float m2 = (rs[4]+rs[5]+rs[6]+rs[7]) * (1.0f/128.0f);
    float var = m2 - m1*m1;
    float xn = (v - m1) * rsqrtf(var + 1e-5f) * w[t] + bia[t];
    float ge = 0.5f * xn * (1.0f + erff(xn * 0.70710678118654752f));
    g_xs[off + (long)b*CKD + t] = ge;
}

// ---------------- host ----------------
extern "C" void kernel_launch(void* const* d_in, const int* in_sizes, int n_in,
                              void* d_out, int out_size) {
    const float* x   = (const float*)d_in[0];
    const float* Awr = (const float*)d_in[1];
    const float* Awi = (const float*)d_in[2];
    const float* Bwr = (const float*)d_in[3];
    const float* Bwi = (const float*)d_in[4];
    const float* Cwr = (const float*)d_in[5];
    const float* Cwi = (const float*)d_in[6];
    const float* lnw = (const float*)d_in[7];
    const float* lnb = (const float*)d_in[8];
    const float* ecs = (const float*)d_in[9];
    const float* ecd = (const float*)d_in[10];
    const float* rce = (const float*)d_in[11];
    const float* rco = (const float*)d_in[12];
    float* out = (float*)d_out;

    static const int NH[13]  = {4096,2048,1024,512,256,128,64,32,16,8,4,2,1};
    static const int LM[13]  = {64,64,64,64,64,64,33,17,9,5,3,2,1};
    static const int SSP[13] = {16,16,8,4,2,2,1,1,1,1,1,1,1};
    long OFF[13];
    OFF[0] = 0;
    for (int l=1; l<13; ++l) OFF[l] = OFF[l-1] + (long)16*NH[l-1]*128;

    k_base<<<16, 256>>>();
    long wthr = (long)3*64*128*128;
    k_wtrans<<<(unsigned)((wthr+255)/256), 256>>>(Awr, Awi, Bwr, Bwi, Cwr, Cwi);

    for (int l=0; l<13; ++l){
        int nh = NH[l], lm = LM[l], ssp = SSP[l], stride = 4096 / nh;
        long nthr = (long)16*nh*16;
        unsigned blk = (unsigned)((nthr + 255) / 256);
        k_decompose<<<blk, 256>>>(l==0 ? x : (const float*)0, l ? OFF[l-1] : 0,
                                  OFF[l], ecs, ecd, nh);
        dim3 gf((lm+15)/16, ssp, 32);
        k_fdft<<<gf, 128>>>(OFF[l], ssp>1 ? 1 : 0, nh, lm, stride);
        if (ssp > 1){
            unsigned rb = (unsigned)(((long)16*lm*128 + 255)/256);
            k_ftred<<<dim3(rb, 2), 256>>>(lm, ssp);
        }
        k_mix<<<dim3(lm, 4), 128>>>(lm);
        int n2 = nh >> 1;
        int gx = (n2 == 0) ? 1 : (n2 + 15)/16;
        k_idft<<<dim3(gx, 16), 128>>>(OFF[l], nh, lm, stride, 1.0f/(float)nh);
    }

    k_lngelu<<<16, 128>>>(lnw, lnb, OFF[12]);

    for (int l=12; l>=0; --l){
        int nh = NH[l];
        long nthr = (long)16*nh*16;
        unsigned blk = (unsigned)((nthr + 255) / 256);
        k_recon<<<blk, 256>>>(OFF[l], OFF[l],
                              l ? (float*)0 : out, l ? OFF[l-1] : 0,
                              rce, rco, nh);
    }
}